// round 15
// baseline (speedup 1.0000x reference)
#include <cuda_runtime.h>
#include <math_constants.h>
#include <math.h>

// Scratch (no allocs allowed): per-block max partials + global 1/max.
#define MAX_BLOCKS 8192
__device__ float g_partial[MAX_BLOCKS];
__device__ float g_invmax;

__device__ __forceinline__ float hw_tanh(float x) {
    float r;
    asm("tanh.approx.f32 %0, %1;" : "=f"(r) : "f"(x));
    return r;
}

// Rare-path correction: tanh(k*cross)*theta_clamped - sign(cross)*theta_true
__device__ __forceinline__ float corr_term(float dx0, float dy0,
                                           float dx1, float dy1, float crossv) {
    const float k = 100000.0f;
    const float ANG_LO = 4.472136e-3f;   // acos(1-1e-5)
    const float ANG_HI = 3.1371205f;     // pi - acos(1-1e-5)
    float dotv = fmaf(dx0, dx1, dy0 * dy1);
    float ay = fabsf(crossv);
    float ax = fabsf(dotv);
    float num = fminf(ax, ay);
    float den = fmaxf(fmaxf(ax, ay), 1e-37f);
    float a = __fdividef(num, den);
    bool big = a > 0.41421356f;
    float ar = __fdividef(a - 1.0f, a + 1.0f);
    float xx = big ? ar : a;
    float z = xx * xx;
    float pl = fmaf(fmaf(fmaf(8.05374449538e-2f, z,
                              -1.38776856032e-1f), z,
                         1.99777106478e-1f), z,
                    -3.33329491539e-1f);
    float r = fmaf(xx * z, pl, xx);
    if (big) r += 0.78539816340f;
    if (ay > ax) r = 1.57079632679f - r;
    if (dotv < 0.0f) r = 3.14159265359f - r;
    float rc = fminf(fmaxf(r, ANG_LO), ANG_HI);
    float sgn = hw_tanh(k * crossv);
    float signed_t = (crossv < 0.0f) ? -r : r;
    return fmaf(sgn, rc, -signed_t);
}

// Kernel 1: FOUR threads per pixel, each covering a quarter of the vertex
// pairs. Warp-level quarter assignment keeps sc[j] loads broadcast
// (conflict-free): block = 256 threads = 8 warps covering 64 pixels;
// warps {2q, 2q+1} -> quarter q of pixels 0-31 / 32-63.
__global__ __launch_bounds__(256) void prod_kernel(
    const float2* __restrict__ contour, int N,
    int Sv, float invS, float* __restrict__ out) {
    extern __shared__ char sraw[];
    float4* s_part = (float4*)sraw;                        // 3*64 combine slots
    float2* sc = (float2*)(sraw + 192 * sizeof(float4));   // N+1 vertices
    __shared__ float warp_red[8];

    const int tid = threadIdx.x;
    for (int i = tid; i <= N; i += blockDim.x)
        sc[i] = contour[i == N ? 0 : i];
    __syncthreads();

    const int warp = tid >> 5;
    const int lane = tid & 31;
    const int quarter = warp >> 1;              // 0..3
    const int pix_in_blk = ((warp & 1) << 5) + lane;   // 0..63
    const int p = blockIdx.x * 64 + pix_in_blk;
    const int npix = Sv * Sv;
    const int jbeg = (N * quarter) >> 2;
    const int jend = (N * (quarter + 1)) >> 2;
    const bool active = p < npix;

    float mn2 = CUDART_INF_F, wc = 0.0f;
    int W = 0;
    float val = -CUDART_INF_F;

    if (active) {
        const float px = (float)(p / Sv) * invS;
        const float py = (float)(p % Sv) * invS;
        // product-form trigger: cross^2 < K2 * d2p * d2 covers the acos
        // clamp region exactly (sin^2 theta < 2e-5), K2 with 5% margin;
        // CMIN2 covers unsaturated tanh (|cross| < 1e-4).
        const float K2 = 2.1e-5f;
        const float CMIN2 = 1.1e-8f;

        float2 c0 = sc[jbeg];
        float dx0 = c0.x - px;
        float dy0 = c0.y - py;
        float d2p = fmaf(dx0, dx0, dy0 * dy0);
        mn2 = d2p;
        bool g0 = dy0 > 0.0f;

        #pragma unroll 4
        for (int j = jbeg; j < jend; j++) {
            float2 c = sc[j + 1];
            float dx1 = c.x - px;
            float dy1 = c.y - py;
            float d2 = fmaf(dx1, dx1, dy1 * dy1);
            mn2 = fminf(mn2, d2);
            float crossv = fmaf(dy0, dx1, -dx0 * dy1);

            bool g1 = dy1 > 0.0f;
            if (g0 != g1) {
                if (g0) { if (crossv > 0.0f) W++; }
                else    { if (crossv < 0.0f) W--; }
            }

            float cr2 = crossv * crossv;
            float tau2 = fmaf(d2p * d2, K2, CMIN2);
            if (cr2 < tau2)
                wc += corr_term(dx0, dy0, dx1, dy1, crossv);

            dx0 = dx1; dy0 = dy1; d2p = d2; g0 = g1;
        }
    }

    // Combine the four quarters through smem.
    if (quarter != 0 && active)
        s_part[(quarter - 1) * 64 + pix_in_blk] =
            make_float4(mn2, wc, (float)W, 0.0f);
    __syncthreads();
    if (quarter == 0 && active) {
        #pragma unroll
        for (int q = 0; q < 3; q++) {
            float4 o = s_part[q * 64 + pix_in_blk];
            mn2 = fminf(mn2, o.x);
            wc += o.y;
            W += (int)o.z;
        }
        val = fmaf(6.283185307179586f, (float)W, wc)
              * 0.15915494309189535f * sqrtf(mn2);
        out[p] = val;
    }

    // Block max reduction (non-quarter-0 threads hold -inf).
    float m = val;
    #pragma unroll
    for (int o = 16; o > 0; o >>= 1)
        m = fmaxf(m, __shfl_xor_sync(0xffffffffu, m, o));
    if (lane == 0) warp_red[warp] = m;
    __syncthreads();
    if (tid == 0) {
        float bm = warp_red[0];
        #pragma unroll
        for (int i = 1; i < 8; i++) bm = fmaxf(bm, warp_red[i]);
        g_partial[blockIdx.x] = bm;
    }
}

// Kernel 2: reduce block partials -> 1/max (single block).
__global__ void max_kernel(int nb) {
    __shared__ float red[32];
    float m = -CUDART_INF_F;
    for (int i = threadIdx.x; i < nb; i += blockDim.x)
        m = fmaxf(m, g_partial[i]);
    #pragma unroll
    for (int o = 16; o > 0; o >>= 1)
        m = fmaxf(m, __shfl_xor_sync(0xffffffffu, m, o));
    if ((threadIdx.x & 31) == 0) red[threadIdx.x >> 5] = m;
    __syncthreads();
    if (threadIdx.x == 0) {
        float bm = red[0];
        int nw = blockDim.x >> 5;
        for (int i = 1; i < nw; i++) bm = fmaxf(bm, red[i]);
        g_invmax = 1.0f / bm;
    }
}

// Kernel 3: normalize (vectorized float4; block 0 covers scalar tail).
__global__ void norm_kernel(float4* __restrict__ out4, float* __restrict__ outf,
                            int nvec, int npix) {
    const float inv = g_invmax;
    int i = blockIdx.x * blockDim.x + threadIdx.x;
    if (i < nvec) {
        float4 v = out4[i];
        v.x *= inv; v.y *= inv; v.z *= inv; v.w *= inv;
        out4[i] = v;
    }
    int tail = npix - nvec * 4;
    if (blockIdx.x == 0 && threadIdx.x < tail)
        outf[nvec * 4 + threadIdx.x] *= inv;
}

extern "C" void kernel_launch(void* const* d_in, const int* in_sizes, int n_in,
                              void* d_out, int out_size) {
    const float2* contour = (const float2*)d_in[0];
    const int N = in_sizes[0] / 2;   // (N, 2) float32
    int Sv = (int)(sqrt((double)out_size) + 0.5);
    float invS = 1.0f / (float)Sv;
    int npix = Sv * Sv;

    float* out = (float*)d_out;
    int blocks = (npix + 63) / 64;                 // 2304 for S=384
    size_t smem = 192 * sizeof(float4) + (size_t)(N + 1) * sizeof(float2);

    prod_kernel<<<blocks, 256, smem>>>(contour, N, Sv, invS, out);
    max_kernel<<<1, 1024>>>(blocks);

    int nvec = npix / 4;
    int nthr = 256;
    int vb = (nvec + nthr - 1) / nthr;
    if (vb < 1) vb = 1;
    norm_kernel<<<vb, nthr>>>((float4*)out, out, nvec, npix);
}